// round 6
// baseline (speedup 1.0000x reference)
#include <cuda_runtime.h>
#include <math.h>

#define VDIM 1024
#define MAXB 8
#define MAXT 256
#define MAXU 65

// Scratch (allocation-free rule: __device__ globals)
__device__ float g_lp_blank[MAXB * MAXT * MAXU];          // [b][t][u]
__device__ float g_lp_label[MAXB * MAXT * (MAXU - 1)];    // [b][t][u<U-1]
__device__ float g_loss[MAXB];

__device__ __forceinline__ float ex2f(float x) { float r; asm("ex2.approx.f32 %0,%1;" : "=f"(r) : "f"(x)); return r; }
__device__ __forceinline__ float lg2f(float x) { float r; asm("lg2.approx.f32 %0,%1;" : "=f"(r) : "f"(x)); return r; }

// ---------------------------------------------------------------------------
// Kernel 1: per-row (b,t,u) log-softmax over V=1024, emit blank & label lp.
// One warp per row, 32 floats/lane in registers, warp-shuffle reductions.
// Rows never consumed by the DP (t >= act_len || u > label_len) are skipped
// BEFORE any load: ~40% DRAM traffic saved.
// ---------------------------------------------------------------------------
__global__ void __launch_bounds__(256) softmax_pick_kernel(
    const float* __restrict__ acts, const int* __restrict__ labels,
    const int* __restrict__ act_lens, const int* __restrict__ label_lens,
    int B, int T, int U, int nRows)
{
    int gw   = (blockIdx.x * blockDim.x + threadIdx.x) >> 5;  // global warp id = row
    int lane = threadIdx.x & 31;
    if (gw >= nRows) return;

    // row -> (b,t,u)
    int u  = gw % U;
    int bt = gw / U;
    int t  = bt % T;
    int b  = bt / T;

    // skip rows the DP never reads (uniform per warp)
    if (t >= __ldg(&act_lens[b]) || u > __ldg(&label_lens[b])) return;

    const float4* row = reinterpret_cast<const float4*>(acts) + (size_t)gw * (VDIM / 4);

    float4 v[8];
#pragma unroll
    for (int k = 0; k < 8; ++k)
        v[k] = row[lane + 32 * k];            // coalesced: lane-contiguous float4s

    // max over 1024
    float m = -INFINITY;
#pragma unroll
    for (int k = 0; k < 8; ++k)
        m = fmaxf(m, fmaxf(fmaxf(v[k].x, v[k].y), fmaxf(v[k].z, v[k].w)));
#pragma unroll
    for (int o = 16; o > 0; o >>= 1)
        m = fmaxf(m, __shfl_xor_sync(0xffffffffu, m, o));

    // sum exp(x - m)
    float s = 0.f;
#pragma unroll
    for (int k = 0; k < 8; ++k) {
        s += __expf(v[k].x - m);
        s += __expf(v[k].y - m);
        s += __expf(v[k].z - m);
        s += __expf(v[k].w - m);
    }
#pragma unroll
    for (int o = 16; o > 0; o >>= 1)
        s += __shfl_xor_sync(0xffffffffu, s, o);

    float logZ = m + __logf(s);

    // blank = element 0 (lane 0, k 0, comp x)
    if (lane == 0)
        g_lp_blank[gw] = v[0].x - logZ;

    // label gather (u < U-1 only)
    if (u < U - 1) {
        int lbl = labels[b * (U - 1) + u];    // in [1, V)
        int q   = lbl >> 2;                   // which float4 globally
        if (lane == (q & 31)) {
            int kq = q >> 5;
            int c  = lbl & 3;
#pragma unroll
            for (int k = 0; k < 8; ++k)
                if (k == kq) {                // static unroll keeps v[] in regs
                    float4 w = v[k];
                    float  x = (c == 0) ? w.x : (c == 1) ? w.y : (c == 2) ? w.z : w.w;
                    g_lp_label[(b * T + t) * (U - 1) + u] = x - logZ;
                }
        }
    }
}

// ---------------------------------------------------------------------------
// Kernel 2: alpha wavefront DP, one block per batch; DP runs in warp 0 only.
// Lane l owns u in {2l, 2l+1}; lane 31 additionally owns u=64.
// Cross-lane dep (u-1 at diag d-1) via one __shfl_up per diagonal; the
// t-direction dep stays in the lane's own register -> no barriers in the loop.
// All values kept in log2 domain (scaled at preload) so logaddexp is
// fmax + EX2 + LG2 + adds on the critical path.
// Shared arrays padded to stride 66 so anti-diagonal access is <=2-way
// bank-conflicted instead of 32-way.
// ---------------------------------------------------------------------------
#define DPS 66   // padded row stride in shared

extern __shared__ __align__(16) float smem2[];

__device__ __forceinline__ float l2add(float x, float y)
{
    float mx = fmaxf(x, y);
    float mn = fminf(x, y);
    return mx + lg2f(1.f + ex2f(mn - mx));
}

__global__ void __launch_bounds__(256) alpha_kernel(
    const int* __restrict__ act_lens, const int* __restrict__ label_lens,
    int T, int U)
{
    const float LOG2E = 1.44269504088896340736f;
    const float LN2   = 0.69314718055994530942f;

    int b   = blockIdx.x;
    int tid = threadIdx.x;
    int U1  = U - 1;

    float* sb = smem2;              // blank slice  [T][DPS]
    float* sl = smem2 + T * DPS;    // label slice  [T][DPS]

    // preload + scale to log2 domain (all 256 threads)
    {
        const float* gb = g_lp_blank + (size_t)b * T * U;
        int nb = T * U;
        for (int i = tid; i < nb; i += blockDim.x) {
            int t = i / U, u = i - t * U;
            sb[t * DPS + u] = gb[i] * LOG2E;
        }
        const float* gl = g_lp_label + (size_t)b * T * U1;
        int nl = T * U1;
        for (int i = tid; i < nl; i += blockDim.x) {
            int t = i / U1, j = i - t * U1;
            sl[t * DPS + j] = gl[i] * LOG2E;
        }
    }
    int tcap = act_lens[b] - 1;
    int ucap = label_lens[b];
    __syncthreads();

    if (tid >= 32) return;          // DP is single-warp

    int  l  = tid;
    int  u0 = 2 * l, u1 = 2 * l + 1;
    bool L31 = (l == 31);

    float a0 = 0.f, a1 = 0.f, a2 = 0.f;   // log2-domain alpha at current diag

    if (l == 0 && tcap == 0 && ucap == 0)
        g_loss[b] = -(sb[0]) * LN2;       // degenerate (can't occur here, guard)

    int D = T + U - 1;
    for (int d = 1; d < D; ++d) {
        float p_up = __shfl_up_sync(0xffffffffu, a1, 1);  // lane l-1's old a1 (u=2l-1)

        float n0 = a0, n1 = a1, n2 = a2;

        // cell u0 = 2l
        {
            int t = d - u0;
            if (t >= 0 && t < T) {
                float a;
                if (t == 0)            a = p_up + sl[u0 - 1];
                else if (u0 == 0)      a = a0 + sb[(t - 1) * DPS];
                else {
                    float x = a0   + sb[(t - 1) * DPS + u0];
                    float y = p_up + sl[t * DPS + u0 - 1];
                    a = l2add(x, y);
                }
                n0 = a;
                if (t == tcap && u0 == ucap)
                    g_loss[b] = -(a + sb[tcap * DPS + u0]) * LN2;
            }
        }
        // cell u1 = 2l+1  (left neighbour u0 is own old a0)
        {
            int t = d - u1;
            if (t >= 0 && t < T) {
                float a;
                if (t == 0)            a = a0 + sl[u1 - 1];
                else {
                    float x = a1 + sb[(t - 1) * DPS + u1];
                    float y = a0 + sl[t * DPS + u1 - 1];
                    a = l2add(x, y);
                }
                n1 = a;
                if (t == tcap && u1 == ucap)
                    g_loss[b] = -(a + sb[tcap * DPS + u1]) * LN2;
            }
        }
        // cell u2 = 64 (lane 31 only; left neighbour u=63 is own old a1)
        if (L31) {
            int t = d - 64;
            if (t >= 0 && t < T) {
                float a;
                if (t == 0)            a = a1 + sl[63];
                else {
                    float x = a2 + sb[(t - 1) * DPS + 64];
                    float y = a1 + sl[t * DPS + 63];
                    a = l2add(x, y);
                }
                n2 = a;
                if (t == tcap && 64 == ucap)
                    g_loss[b] = -(a + sb[tcap * DPS + 64]) * LN2;
            }
        }

        a0 = n0; a1 = n1; a2 = n2;
    }
}

// ---------------------------------------------------------------------------
// Kernel 3: mean of per-batch costs -> d_out[0]
// ---------------------------------------------------------------------------
__global__ void finalize_kernel(float* __restrict__ out, int B)
{
    int lane = threadIdx.x;
    float v = (lane < B) ? g_loss[lane] : 0.f;
#pragma unroll
    for (int o = 16; o > 0; o >>= 1)
        v += __shfl_xor_sync(0xffffffffu, v, o);
    if (lane == 0)
        out[0] = v / (float)B;
}

// ---------------------------------------------------------------------------
extern "C" void kernel_launch(void* const* d_in, const int* in_sizes, int n_in,
                              void* d_out, int out_size)
{
    const float* acts       = (const float*)d_in[0];
    const int*   labels     = (const int*)d_in[1];
    const int*   act_lens   = (const int*)d_in[2];
    const int*   label_lens = (const int*)d_in[3];

    int B  = in_sizes[2];                 // 8
    int U1 = in_sizes[1] / B;             // 64
    int U  = U1 + 1;                      // 65
    long long total = in_sizes[0];
    int T  = (int)(total / ((long long)B * U * VDIM));   // 256

    int nRows = B * T * U;                                // 133,120
    int blocks = (nRows + 7) / 8;                         // 8 warps / block
    softmax_pick_kernel<<<blocks, 256>>>(acts, labels, act_lens, label_lens,
                                         B, T, U, nRows);

    int smemBytes = 2 * T * DPS * (int)sizeof(float);     // 135,168 B
    cudaFuncSetAttribute(alpha_kernel,
                         cudaFuncAttributeMaxDynamicSharedMemorySize, smemBytes);
    alpha_kernel<<<B, 256, smemBytes>>>(act_lens, label_lens, T, U);

    finalize_kernel<<<1, 32>>>((float*)d_out, B);
}

// round 7
// speedup vs baseline: 1.7352x; 1.7352x over previous
#include <cuda_runtime.h>
#include <math.h>

#define VDIM 1024
#define MAXB 8
#define MAXT 256
#define MAXU 65
#define DPS  66          // padded row stride in shared (2-way max bank conflict on diagonals)
#define NEG_BIG (-1.0e30f)

// Scratch (allocation-free rule: __device__ globals). Values stored in LOG2 domain.
__device__ float g_lp_blank[MAXB * MAXT * MAXU];          // [b][t][u]   (log2)
__device__ float g_lp_label[MAXB * MAXT * (MAXU - 1)];    // [b][t][u]   (log2)
__device__ float g_loss[MAXB];

__device__ __forceinline__ float ex2f(float x) { float r; asm("ex2.approx.f32 %0,%1;" : "=f"(r) : "f"(x)); return r; }
__device__ __forceinline__ float lg2f(float x) { float r; asm("lg2.approx.f32 %0,%1;" : "=f"(r) : "f"(x)); return r; }

// log2-domain logaddexp: log2(2^x + 2^y)
__device__ __forceinline__ float l2add(float x, float y)
{
    float mx = fmaxf(x, y);
    float mn = fminf(x, y);
    return mx + lg2f(1.f + ex2f(mn - mx));
}

// ---------------------------------------------------------------------------
// Kernel 1: per-row (b,t,u) log-softmax over V=1024, emit blank & label lp
// in log2 domain. One warp per row, 32 floats/lane in registers. Rows the DP
// never reads (t >= act_len || u > label_len) are skipped before any load.
// ---------------------------------------------------------------------------
__global__ void __launch_bounds__(256) softmax_pick_kernel(
    const float* __restrict__ acts, const int* __restrict__ labels,
    const int* __restrict__ act_lens, const int* __restrict__ label_lens,
    int B, int T, int U, int nRows)
{
    const float LOG2E = 1.44269504088896340736f;

    int gw   = (blockIdx.x * blockDim.x + threadIdx.x) >> 5;  // global warp id = row
    int lane = threadIdx.x & 31;
    if (gw >= nRows) return;

    // row -> (b,t,u)
    int u  = gw % U;
    int bt = gw / U;
    int t  = bt % T;
    int b  = bt / T;

    if (t >= __ldg(&act_lens[b]) || u > __ldg(&label_lens[b])) return;

    const float4* row = reinterpret_cast<const float4*>(acts) + (size_t)gw * (VDIM / 4);

    float4 v[8];
#pragma unroll
    for (int k = 0; k < 8; ++k)
        v[k] = row[lane + 32 * k];

    float m = -INFINITY;
#pragma unroll
    for (int k = 0; k < 8; ++k)
        m = fmaxf(m, fmaxf(fmaxf(v[k].x, v[k].y), fmaxf(v[k].z, v[k].w)));
#pragma unroll
    for (int o = 16; o > 0; o >>= 1)
        m = fmaxf(m, __shfl_xor_sync(0xffffffffu, m, o));

    float s = 0.f;
#pragma unroll
    for (int k = 0; k < 8; ++k) {
        s += __expf(v[k].x - m);
        s += __expf(v[k].y - m);
        s += __expf(v[k].z - m);
        s += __expf(v[k].w - m);
    }
#pragma unroll
    for (int o = 16; o > 0; o >>= 1)
        s += __shfl_xor_sync(0xffffffffu, s, o);

    float logZ = m + __logf(s);

    if (lane == 0)
        g_lp_blank[gw] = (v[0].x - logZ) * LOG2E;

    if (u < U - 1) {
        int lbl = labels[b * (U - 1) + u];
        int q   = lbl >> 2;
        if (lane == (q & 31)) {
            int kq = q >> 5;
            int c  = lbl & 3;
#pragma unroll
            for (int k = 0; k < 8; ++k)
                if (k == kq) {
                    float4 w = v[k];
                    float  x = (c == 0) ? w.x : (c == 1) ? w.y : (c == 2) ? w.z : w.w;
                    g_lp_label[(b * T + t) * (U - 1) + u] = (x - logZ) * LOG2E;
                }
        }
    }
}

// ---------------------------------------------------------------------------
// Kernel 2: alpha wavefront DP, one block per batch; DP in warp 0, branchless.
//   sb[r][u] = lpb(r-1, u) for r in [1,T], row 0 = -1e30 sentinel.
//   sl[t][c] = lpl(t, c-1) for c in [1,64], col 0 = -1e30 sentinel.
// Unified recurrence with sentinel suppression handles t==0 / u==0 edges;
// out-of-range cells use clamped addresses (finite garbage, never consumed).
// Loss captured via predicated selects; no branches in the diagonal loop.
// ---------------------------------------------------------------------------
extern __shared__ __align__(16) float smem2[];

__global__ void __launch_bounds__(256) alpha_kernel(
    const int* __restrict__ act_lens, const int* __restrict__ label_lens,
    int T, int U)
{
    const float LN2 = 0.69314718055994530942f;

    int b    = blockIdx.x;
    int tid  = threadIdx.x;
    int lane = tid & 31;
    int warp = tid >> 5;
    int U1   = U - 1;

    float* sb = smem2;                    // (T+1) x DPS
    float* sl = smem2 + (T + 1) * DPS;    // T x DPS

    const float* gb = g_lp_blank + (size_t)b * T * U;
    const float* gl = g_lp_label + (size_t)b * T * U1;

    // preload: one warp per row, coalesced global reads, stride-1 smem writes
    for (int r = warp; r < T + 1; r += 8) {
        if (r == 0) {
            for (int u = lane; u < U; u += 32) sb[u] = NEG_BIG;
        } else {
            for (int u = lane; u < U; u += 32) sb[r * DPS + u] = gb[(r - 1) * U + u];
        }
    }
    for (int t = warp; t < T; t += 8) {
        if (lane == 0) sl[t * DPS] = NEG_BIG;
        for (int c = lane; c < U1; c += 32) sl[t * DPS + 1 + c] = gl[t * U1 + c];
    }

    int tcap = act_lens[b] - 1;
    int ucap = label_lens[b];
    __syncthreads();

    if (tid >= 32) return;

    int l  = tid;
    int u0 = 2 * l, u1 = 2 * l + 1;          // lane 31 also owns u=64 (slot 2)

    float a0 = 0.f, a1 = 0.f, a2 = 0.f;      // alpha at current diagonal (log2)
    float r0 = 0.f, r1 = 0.f, r2 = 0.f;      // captured alpha(tcap, u)

    int d0cap = tcap + u0;
    int d1cap = tcap + u1;
    int d2cap = tcap + 64;
    int D     = tcap + ucap;                 // last diagonal needed

    for (int d = 1; d <= D; ++d) {
        float p = __shfl_up_sync(0xffffffffu, a1, 1);   // alpha(.., u0-1) from lane l-1

        // cell u0 = 2l
        int t  = d - u0;
        int tb = min(max(t, 0), T);
        int tl = min(tb, T - 1);
        float x0 = a0 + sb[tb * DPS + u0];
        float y0 = p  + sl[tl * DPS + u0];
        float n0 = l2add(x0, y0);

        // cell u1 = 2l+1 (left neighbour is own old a0)
        int t1  = d - u1;
        int tb1 = min(max(t1, 0), T);
        int tl1 = min(tb1, T - 1);
        float x1 = a1 + sb[tb1 * DPS + u1];
        float y1 = a0 + sl[tl1 * DPS + u1];
        float n1 = l2add(x1, y1);

        // cell u2 = 64 (computed by all lanes, committed only on lane 31)
        int t2  = d - 64;
        int tb2 = min(max(t2, 0), T);
        int tl2 = min(tb2, T - 1);
        float x2 = a2 + sb[tb2 * DPS + 64];
        float y2 = a1 + sl[tl2 * DPS + 64];
        float n2 = l2add(x2, y2);

        r0 = (d == d0cap) ? n0 : r0;
        r1 = (d == d1cap) ? n1 : r1;
        r2 = (d == d2cap) ? n2 : r2;

        a0 = n0; a1 = n1; a2 = n2;
    }

    // exactly one (lane, slot) owns (tcap, ucap)
    float res = 0.f; int hit = 0;
    if (u0 == ucap)                  { res = r0; hit = 1; }
    else if (u1 == ucap)             { res = r1; hit = 1; }
    else if (l == 31 && ucap == 64)  { res = r2; hit = 1; }
    if (hit)
        g_loss[b] = -(res + sb[(tcap + 1) * DPS + ucap]) * LN2;
}

// ---------------------------------------------------------------------------
// Kernel 3: mean of per-batch costs -> d_out[0]
// ---------------------------------------------------------------------------
__global__ void finalize_kernel(float* __restrict__ out, int B)
{
    int lane = threadIdx.x;
    float v = (lane < B) ? g_loss[lane] : 0.f;
#pragma unroll
    for (int o = 16; o > 0; o >>= 1)
        v += __shfl_xor_sync(0xffffffffu, v, o);
    if (lane == 0)
        out[0] = v / (float)B;
}

// ---------------------------------------------------------------------------
extern "C" void kernel_launch(void* const* d_in, const int* in_sizes, int n_in,
                              void* d_out, int out_size)
{
    const float* acts       = (const float*)d_in[0];
    const int*   labels     = (const int*)d_in[1];
    const int*   act_lens   = (const int*)d_in[2];
    const int*   label_lens = (const int*)d_in[3];

    int B  = in_sizes[2];                 // 8
    int U1 = in_sizes[1] / B;             // 64
    int U  = U1 + 1;                      // 65
    long long total = in_sizes[0];
    int T  = (int)(total / ((long long)B * U * VDIM));   // 256

    int nRows = B * T * U;
    int blocks = (nRows + 7) / 8;
    softmax_pick_kernel<<<blocks, 256>>>(acts, labels, act_lens, label_lens,
                                         B, T, U, nRows);

    int smemBytes = ((T + 1) + T) * DPS * (int)sizeof(float);   // 135,432 B
    cudaFuncSetAttribute(alpha_kernel,
                         cudaFuncAttributeMaxDynamicSharedMemorySize, smemBytes);
    alpha_kernel<<<B, 256, smemBytes>>>(act_lens, label_lens, T, U);

    finalize_kernel<<<1, 32>>>((float*)d_out, B);
}

// round 8
// speedup vs baseline: 1.8471x; 1.0645x over previous
#include <cuda_runtime.h>
#include <math.h>

#define VDIM 1024
#define MAXB 8
#define MAXT 256
#define MAXU 65
#define DPS  66          // padded row stride in shared (<=2-way bank conflict on diagonals)
#define NEG_BIG (-1.0e30f)

// Scratch (allocation-free rule: __device__ globals). Values stored in LOG2 domain.
__device__ float g_lp_blank[MAXB * MAXT * MAXU];          // [b][t][u]   (log2)
__device__ float g_lp_label[MAXB * MAXT * (MAXU - 1)];    // [b][t][u]   (log2)
__device__ float g_loss[MAXB];

__device__ __forceinline__ float ex2f(float x) { float r; asm("ex2.approx.f32 %0,%1;" : "=f"(r) : "f"(x)); return r; }
__device__ __forceinline__ float lg2f(float x) { float r; asm("lg2.approx.f32 %0,%1;" : "=f"(r) : "f"(x)); return r; }

// log2-domain logaddexp: log2(2^x + 2^y)
__device__ __forceinline__ float l2add(float x, float y)
{
    float mx = fmaxf(x, y);
    float mn = fminf(x, y);
    return mx + lg2f(1.f + ex2f(mn - mx));
}

// ---------------------------------------------------------------------------
// Kernel 1: per-row (b,t,u) log-softmax over V=1024, emit blank & label lp
// in log2 domain. One warp per row, 32 floats/lane in registers. Rows the DP
// never reads (t >= act_len || u > label_len) are skipped before any load.
// ---------------------------------------------------------------------------
__global__ void __launch_bounds__(256) softmax_pick_kernel(
    const float* __restrict__ acts, const int* __restrict__ labels,
    const int* __restrict__ act_lens, const int* __restrict__ label_lens,
    int B, int T, int U, int nRows)
{
    const float LOG2E = 1.44269504088896340736f;

    int gw   = (blockIdx.x * blockDim.x + threadIdx.x) >> 5;  // global warp id = row
    int lane = threadIdx.x & 31;
    if (gw >= nRows) return;

    // row -> (b,t,u)
    int u  = gw % U;
    int bt = gw / U;
    int t  = bt % T;
    int b  = bt / T;

    if (t >= __ldg(&act_lens[b]) || u > __ldg(&label_lens[b])) return;

    const float4* row = reinterpret_cast<const float4*>(acts) + (size_t)gw * (VDIM / 4);

    float4 v[8];
#pragma unroll
    for (int k = 0; k < 8; ++k)
        v[k] = row[lane + 32 * k];

    float m = -INFINITY;
#pragma unroll
    for (int k = 0; k < 8; ++k)
        m = fmaxf(m, fmaxf(fmaxf(v[k].x, v[k].y), fmaxf(v[k].z, v[k].w)));
#pragma unroll
    for (int o = 16; o > 0; o >>= 1)
        m = fmaxf(m, __shfl_xor_sync(0xffffffffu, m, o));

    float s = 0.f;
#pragma unroll
    for (int k = 0; k < 8; ++k) {
        s += __expf(v[k].x - m);
        s += __expf(v[k].y - m);
        s += __expf(v[k].z - m);
        s += __expf(v[k].w - m);
    }
#pragma unroll
    for (int o = 16; o > 0; o >>= 1)
        s += __shfl_xor_sync(0xffffffffu, s, o);

    float logZ = m + __logf(s);

    if (lane == 0)
        g_lp_blank[gw] = (v[0].x - logZ) * LOG2E;

    if (u < U - 1) {
        int lbl = labels[b * (U - 1) + u];
        int q   = lbl >> 2;
        if (lane == (q & 31)) {
            int kq = q >> 5;
            int c  = lbl & 3;
#pragma unroll
            for (int k = 0; k < 8; ++k)
                if (k == kq) {
                    float4 w = v[k];
                    float  x = (c == 0) ? w.x : (c == 1) ? w.y : (c == 2) ? w.z : w.w;
                    g_lp_label[(b * T + t) * (U - 1) + u] = (x - logZ) * LOG2E;
                }
        }
    }
}

// ---------------------------------------------------------------------------
// Kernel 2: alpha wavefront DP, one block per batch; DP in warp 0, branchless,
// with one-iteration-ahead software pipelining of all 6 smem operands so LDS
// latency overlaps the shfl/ex2/lg2 critical chain.
//   sb[r][u] = lpb(r-1, u) for r in [1,T], row 0 = -1e30 sentinel.
//   sl[t][c] = lpl(t, c-1) for c in [1,64], col 0 = -1e30 sentinel.
// ---------------------------------------------------------------------------
extern __shared__ __align__(16) float smem2[];

__global__ void __launch_bounds__(256) alpha_kernel(
    const int* __restrict__ act_lens, const int* __restrict__ label_lens,
    int T, int U)
{
    const float LN2 = 0.69314718055994530942f;

    int b    = blockIdx.x;
    int tid  = threadIdx.x;
    int lane = tid & 31;
    int warp = tid >> 5;
    int U1   = U - 1;

    float* sb = smem2;                    // (T+1) x DPS
    float* sl = smem2 + (T + 1) * DPS;    // T x DPS

    const float* gb = g_lp_blank + (size_t)b * T * U;
    const float* gl = g_lp_label + (size_t)b * T * U1;

    // preload: one warp per row, coalesced global reads, stride-1 smem writes
    for (int r = warp; r < T + 1; r += 8) {
        if (r == 0) {
            for (int u = lane; u < U; u += 32) sb[u] = NEG_BIG;
        } else {
            for (int u = lane; u < U; u += 32) sb[r * DPS + u] = gb[(r - 1) * U + u];
        }
    }
    for (int t = warp; t < T; t += 8) {
        if (lane == 0) sl[t * DPS] = NEG_BIG;
        for (int c = lane; c < U1; c += 32) sl[t * DPS + 1 + c] = gl[t * U1 + c];
    }

    int tcap = act_lens[b] - 1;
    int ucap = label_lens[b];
    __syncthreads();

    if (tid >= 32) return;

    int l  = tid;
    int u0 = 2 * l, u1 = 2 * l + 1;          // lane 31 also owns u=64 (slot 2)

    float a0 = 0.f, a1 = 0.f, a2 = 0.f;      // alpha at current diagonal (log2)
    float r0 = 0.f, r1 = 0.f, r2 = 0.f;      // captured alpha(tcap, u)

    int d0cap = tcap + u0;
    int d1cap = tcap + u1;
    int d2cap = tcap + 64;
    int D     = tcap + ucap;                 // last diagonal needed

    // --- prime pipeline: operands for d = 1 ---
    float vb0, vl0, vb1, vl1, vb2, vl2;
    {
        int t0 = 1 - u0; int c0 = min(max(t0, 0), T); int m0 = min(c0, T - 1);
        vb0 = sb[c0 * DPS + u0];  vl0 = sl[m0 * DPS + u0];
        int t1 = 1 - u1; int c1 = min(max(t1, 0), T); int m1 = min(c1, T - 1);
        vb1 = sb[c1 * DPS + u1];  vl1 = sl[m1 * DPS + u1];
        int t2 = 1 - 64; int c2 = min(max(t2, 0), T); int m2 = min(c2, T - 1);
        vb2 = sb[c2 * DPS + 64];  vl2 = sl[m2 * DPS + 64];
    }

#pragma unroll 2
    for (int d = 1; d <= D; ++d) {
        // --- prefetch operands for d+1 (independent of this diag's chain) ---
        int t0n = d + 1 - u0; int c0n = min(max(t0n, 0), T); int m0n = min(c0n, T - 1);
        float nvb0 = sb[c0n * DPS + u0], nvl0 = sl[m0n * DPS + u0];
        int t1n = d + 1 - u1; int c1n = min(max(t1n, 0), T); int m1n = min(c1n, T - 1);
        float nvb1 = sb[c1n * DPS + u1], nvl1 = sl[m1n * DPS + u1];
        int t2n = d - 63;     int c2n = min(max(t2n, 0), T); int m2n = min(c2n, T - 1);
        float nvb2 = sb[c2n * DPS + 64], nvl2 = sl[m2n * DPS + 64];

        // --- this diagonal's compute ---
        float p = __shfl_up_sync(0xffffffffu, a1, 1);   // alpha(.., u0-1) from lane l-1

        float n0 = l2add(a0 + vb0, p  + vl0);
        float n1 = l2add(a1 + vb1, a0 + vl1);
        float n2 = l2add(a2 + vb2, a1 + vl2);

        r0 = (d == d0cap) ? n0 : r0;
        r1 = (d == d1cap) ? n1 : r1;
        r2 = (d == d2cap) ? n2 : r2;

        a0 = n0; a1 = n1; a2 = n2;
        vb0 = nvb0; vl0 = nvl0; vb1 = nvb1; vl1 = nvl1; vb2 = nvb2; vl2 = nvl2;
    }

    // exactly one (lane, slot) owns (tcap, ucap)
    float res = 0.f; int hit = 0;
    if (u0 == ucap)                  { res = r0; hit = 1; }
    else if (u1 == ucap)             { res = r1; hit = 1; }
    else if (l == 31 && ucap == 64)  { res = r2; hit = 1; }
    if (hit)
        g_loss[b] = -(res + sb[(tcap + 1) * DPS + ucap]) * LN2;
}

// ---------------------------------------------------------------------------
// Kernel 3: mean of per-batch costs -> d_out[0]
// ---------------------------------------------------------------------------
__global__ void finalize_kernel(float* __restrict__ out, int B)
{
    int lane = threadIdx.x;
    float v = (lane < B) ? g_loss[lane] : 0.f;
#pragma unroll
    for (int o = 16; o > 0; o >>= 1)
        v += __shfl_xor_sync(0xffffffffu, v, o);
    if (lane == 0)
        out[0] = v / (float)B;
}

// ---------------------------------------------------------------------------
extern "C" void kernel_launch(void* const* d_in, const int* in_sizes, int n_in,
                              void* d_out, int out_size)
{
    const float* acts       = (const float*)d_in[0];
    const int*   labels     = (const int*)d_in[1];
    const int*   act_lens   = (const int*)d_in[2];
    const int*   label_lens = (const int*)d_in[3];

    int B  = in_sizes[2];                 // 8
    int U1 = in_sizes[1] / B;             // 64
    int U  = U1 + 1;                      // 65
    long long total = in_sizes[0];
    int T  = (int)(total / ((long long)B * U * VDIM));   // 256

    int nRows = B * T * U;
    int blocks = (nRows + 7) / 8;
    softmax_pick_kernel<<<blocks, 256>>>(acts, labels, act_lens, label_lens,
                                         B, T, U, nRows);

    int smemBytes = ((T + 1) + T) * DPS * (int)sizeof(float);   // 135,432 B
    cudaFuncSetAttribute(alpha_kernel,
                         cudaFuncAttributeMaxDynamicSharedMemorySize, smemBytes);
    alpha_kernel<<<B, 256, smemBytes>>>(act_lens, label_lens, T, U);

    finalize_kernel<<<1, 32>>>((float*)d_out, B);
}